// round 1
// baseline (speedup 1.0000x reference)
#include <cuda_runtime.h>
#include <math.h>

// Problem constants
#define BN   16
#define Hn   256
#define Wn   256
#define IMG  (Hn * Wn)          // 65536
#define NTOT (BN * IMG)         // 1048576
#define NBLK (NTOT / 256)       // 4096
#define BIGF 512.0f             // H + W

// Scratch (device globals — no allocation allowed)
__device__ float    g_sq_in [NTOT];   // d1^2 for mask  (zero = mask==0)
__device__ float    g_sq_out[NTOT];   // d1^2 for 1-mask (zero = mask==1)
__device__ float    g_phi   [NTOT];   // raw signed distance (unnormalized)
__device__ float    g_part  [NBLK * 5];
__device__ unsigned g_maxabs[BN];     // max|phi| per image, as float bits (nonneg)
__device__ int      g_hasany[BN];     // any(mask>0) per image

// ---------------------------------------------------------------------------
// Init: zero the per-image atomics (must run every launch for graph replay)
// ---------------------------------------------------------------------------
__global__ void init_kernel() {
    int t = threadIdx.x;
    if (t < BN) {
        g_maxabs[t] = 0u;       // bits of 0.0f
        g_hasany[t] = 0;
    }
}

// ---------------------------------------------------------------------------
// Vertical pass: per-column 1D distance (down then up), squared, for both
// mask and its complement. Reproduces min(d_up, d_dn, BIG) of the reference:
// when no zero exists in a direction the running value exceeds BIG, and the
// final clamp to BIG makes the results identical.
// grid: (BN, Wn/64), block: 64 threads (thread = one column)
// ---------------------------------------------------------------------------
__global__ __launch_bounds__(64) void vert_kernel(const float* __restrict__ tgt) {
    int b = blockIdx.x;
    int j = blockIdx.y * 64 + threadIdx.x;
    const float* m = tgt + b * IMG;
    float* sin_ = g_sq_in  + b * IMG;
    float* sout = g_sq_out + b * IMG;

    float din = BIGF, dout = BIGF;
    int any = 0;
    // downward pass: distance to nearest zero above (inclusive)
    #pragma unroll 4
    for (int i = 0; i < Hn; i++) {
        float mv = m[i * Wn + j];
        any |= (mv > 0.0f);
        din  = (mv == 0.0f) ? 0.0f : din  + 1.0f;
        dout = (mv != 0.0f) ? 0.0f : dout + 1.0f;
        sin_[i * Wn + j] = din;
        sout[i * Wn + j] = dout;
    }
    din = BIGF; dout = BIGF;
    // upward pass: combine with distance to nearest zero below, clamp, square
    #pragma unroll 4
    for (int i = Hn - 1; i >= 0; i--) {
        float mv = m[i * Wn + j];
        din  = (mv == 0.0f) ? 0.0f : din  + 1.0f;
        dout = (mv != 0.0f) ? 0.0f : dout + 1.0f;
        float a = fminf(fminf(sin_[i * Wn + j], din),  BIGF);
        float c = fminf(fminf(sout[i * Wn + j], dout), BIGF);
        sin_[i * Wn + j] = a * a;
        sout[i * Wn + j] = c * c;
    }
    if (any) atomicOr(&g_hasany[b], 1);
}

// ---------------------------------------------------------------------------
// Horizontal pass: Dsq[i,j] = min_k d1sq[i,k] + (j-k)^2 for both masks.
// Exact early termination: (j-k)^2 grows monotonically with |j-k|, so once
// r*r >= current best for BOTH masks no further k can improve.
// grid: 4096 rows, block: 256 (thread = one output column)
// ---------------------------------------------------------------------------
__global__ __launch_bounds__(256) void horiz_kernel() {
    __shared__ float si[Wn];
    __shared__ float so[Wn];
    __shared__ float red[256];

    int row  = blockIdx.x;        // b*Hn + i
    int j    = threadIdx.x;
    int b    = row >> 8;          // row / Hn
    int base = row * Wn;

    si[j] = g_sq_in [base + j];
    so[j] = g_sq_out[base + j];
    __syncthreads();

    float bi = si[j];
    float bo = so[j];
    for (int r = 1; r < Wn; r++) {
        float off = (float)(r * r);
        if (off >= bi && off >= bo) break;
        int kl = j - r;
        int kr = j + r;
        if (kl >= 0) {
            bi = fminf(bi, si[kl] + off);
            bo = fminf(bo, so[kl] + off);
        }
        if (kr < Wn) {
            bi = fminf(bi, si[kr] + off);
            bo = fminf(bo, so[kr] + off);
        }
    }
    float phi = sqrtf(bo) - sqrtf(bi);   // dist_outside - dist_inside
    g_phi[base + j] = phi;

    // block max of |phi| -> per-image atomicMax (uint bits, valid: nonneg)
    red[j] = fabsf(phi);
    __syncthreads();
    #pragma unroll
    for (int s = 128; s > 0; s >>= 1) {
        if (j < s) red[j] = fmaxf(red[j], red[j + s]);
        __syncthreads();
    }
    if (j == 0) atomicMax(&g_maxabs[b], __float_as_uint(red[0]));
}

// ---------------------------------------------------------------------------
// Reduction stage 1: per-pixel terms -> per-block partial sums (deterministic)
// 5 accumulators: [p*t, p, t, bce, phi_norm*p]
// ---------------------------------------------------------------------------
__global__ __launch_bounds__(256) void reduce1_kernel(const float* __restrict__ pred,
                                                      const float* __restrict__ tgt) {
    int idx = blockIdx.x * 256 + threadIdx.x;
    int b   = idx >> 16;          // idx / IMG

    float x = pred[idx];
    float t = tgt[idx];
    float p = 1.0f / (1.0f + expf(-x));

    float maxabs = __uint_as_float(g_maxabs[b]);
    float phin   = g_hasany[b] ? g_phi[idx] / (maxabs + 1e-8f) : 0.0f;
    float bce    = fmaxf(x, 0.0f) - x * t + log1pf(expf(-fabsf(x)));

    float v0 = p * t;
    float v1 = p;
    float v2 = t;
    float v3 = bce;
    float v4 = phin * p;

    // warp reduction (fixed order within warp -> deterministic)
    #pragma unroll
    for (int o = 16; o > 0; o >>= 1) {
        v0 += __shfl_xor_sync(0xFFFFFFFFu, v0, o);
        v1 += __shfl_xor_sync(0xFFFFFFFFu, v1, o);
        v2 += __shfl_xor_sync(0xFFFFFFFFu, v2, o);
        v3 += __shfl_xor_sync(0xFFFFFFFFu, v3, o);
        v4 += __shfl_xor_sync(0xFFFFFFFFu, v4, o);
    }
    __shared__ float sm[8][5];
    int w = threadIdx.x >> 5;
    int l = threadIdx.x & 31;
    if (l == 0) {
        sm[w][0] = v0; sm[w][1] = v1; sm[w][2] = v2; sm[w][3] = v3; sm[w][4] = v4;
    }
    __syncthreads();
    if (threadIdx.x == 0) {
        float a0 = 0, a1 = 0, a2 = 0, a3 = 0, a4 = 0;
        #pragma unroll
        for (int k = 0; k < 8; k++) {
            a0 += sm[k][0]; a1 += sm[k][1]; a2 += sm[k][2]; a3 += sm[k][3]; a4 += sm[k][4];
        }
        float* out = g_part + blockIdx.x * 5;
        out[0] = a0; out[1] = a1; out[2] = a2; out[3] = a3; out[4] = a4;
    }
}

// ---------------------------------------------------------------------------
// Reduction stage 2: combine 4096 block partials -> scalar loss
// ---------------------------------------------------------------------------
__global__ __launch_bounds__(256) void reduce2_kernel(float* __restrict__ out) {
    __shared__ float sm[5][256];
    int t = threadIdx.x;
    float a0 = 0, a1 = 0, a2 = 0, a3 = 0, a4 = 0;
    for (int i = t; i < NBLK; i += 256) {
        const float* p = g_part + i * 5;
        a0 += p[0]; a1 += p[1]; a2 += p[2]; a3 += p[3]; a4 += p[4];
    }
    sm[0][t] = a0; sm[1][t] = a1; sm[2][t] = a2; sm[3][t] = a3; sm[4][t] = a4;
    __syncthreads();
    #pragma unroll
    for (int s = 128; s > 0; s >>= 1) {
        if (t < s) {
            sm[0][t] += sm[0][t + s];
            sm[1][t] += sm[1][t + s];
            sm[2][t] += sm[2][t + s];
            sm[3][t] += sm[3][t + s];
            sm[4][t] += sm[4][t + s];
        }
        __syncthreads();
    }
    if (t == 0) {
        float inter = sm[0][0];
        float sum_p = sm[1][0];
        float sum_t = sm[2][0];
        float bces  = sm[3][0];
        float bsum  = sm[4][0];

        float smooth   = 1e-6f;
        float dice     = 1.0f - (2.0f * inter + smooth) / (sum_p + sum_t + smooth);
        float boundary = bsum / (float)NTOT;
        float bce      = bces / (float)NTOT;
        // alpha = 0.005, beta = 0.595
        out[0] = 0.405f * dice + 0.595f * boundary + 0.4f * bce;
    }
}

// ---------------------------------------------------------------------------
extern "C" void kernel_launch(void* const* d_in, const int* in_sizes, int n_in,
                              void* d_out, int out_size) {
    const float* pred = (const float*)d_in[0];
    const float* tgt  = (const float*)d_in[1];
    float* out = (float*)d_out;

    init_kernel<<<1, 32>>>();
    {
        dim3 grid(BN, Wn / 64);
        vert_kernel<<<grid, 64>>>(tgt);
    }
    horiz_kernel<<<NBLK, 256>>>();
    reduce1_kernel<<<NBLK, 256>>>(pred, tgt);
    reduce2_kernel<<<1, 256>>>(out);
}

// round 2
// speedup vs baseline: 2.3944x; 2.3944x over previous
#include <cuda_runtime.h>
#include <math.h>

// Problem constants
#define BN    16
#define Hn    256
#define Wn    256
#define IMG   (Hn * Wn)          // 65536
#define NTOT  (BN * IMG)         // 1048576
#define SEG   32                 // rows per segment
#define NSEG  (Hn / SEG)         // 8
#define NCOL  (BN * Wn)          // 4096 total columns
#define NBLK2 (BN * NSEG)        // 128 fused blocks
#define SENT_LO (-100000)
#define SENT_HI ( 100000)

// Scratch (device globals — no allocation allowed)
__device__ int   g_lastz_in  [NSEG * NCOL];
__device__ int   g_lastz_out [NSEG * NCOL];
__device__ int   g_firstz_in [NSEG * NCOL];
__device__ int   g_firstz_out[NSEG * NCOL];
__device__ float g_part      [NBLK2 * 8];   // per-(img,seg): pt,p,t,bce,phi_p,maxabs

// ---------------------------------------------------------------------------
// Carry kernel: per (image, 32-row segment, column) record the row index of
// the last zero and first zero for both the mask ("in": zero where m==0) and
// its complement ("out": zero where m!=0). These are the only values the
// down/up distance recurrences need across segment boundaries.
// grid: (BN, NSEG), block: 256 (thread = column)
// ---------------------------------------------------------------------------
__global__ __launch_bounds__(256) void carry_kernel(const float* __restrict__ tgt) {
    int b = blockIdx.x;
    int s = blockIdx.y;
    int j = threadIdx.x;
    const float* m = tgt + b * IMG;
    int base = s * SEG;

    int lzi = SENT_LO, lzo = SENT_LO, fzi = SENT_HI, fzo = SENT_HI;
    #pragma unroll
    for (int r = 0; r < SEG; r++) {
        int i = base + r;
        float mv = m[i * Wn + j];
        if (mv == 0.0f) { lzi = i; fzi = min(fzi, i); }
        else            { lzo = i; fzo = min(fzo, i); }
    }
    int col = b * Wn + j;
    g_lastz_in  [s * NCOL + col] = lzi;
    g_lastz_out [s * NCOL + col] = lzo;
    g_firstz_in [s * NCOL + col] = fzi;
    g_firstz_out[s * NCOL + col] = fzo;
}

// ---------------------------------------------------------------------------
// Fused kernel: for one (image, 32-row band):
//   1. resolve vertical EDT exactly using cross-segment carries (int math)
//   2. horizontal pass min_k d1sq[k]+(j-k)^2 with exact early termination,
//      entirely in shared memory
//   3. per-pixel loss terms (sigmoid, dice sums, BCE, phi*p, max|phi|)
//   4. block reduction -> per-block partials (deterministic, no atomics)
// grid: (BN, NSEG), block: 256 (thread = column)
// Note: min(din,dn,512)^2 reproduces the reference's BIG clamp exactly; the
// sentinel offsets make "no zero in this direction" exceed 512 before clamp.
// ---------------------------------------------------------------------------
__global__ __launch_bounds__(256) void fused_kernel(const float* __restrict__ pred,
                                                    const float* __restrict__ tgt) {
    __shared__ int s_in [SEG][Wn];   // d1^2 for mask (dist_inside)
    __shared__ int s_out[SEG][Wn];   // d1^2 for complement (dist_outside)
    __shared__ float s_red[8][8];

    int b = blockIdx.x;
    int s = blockIdx.y;
    int j = threadIdx.x;
    int col = b * Wn + j;
    int base = s * SEG;

    // Resolve carries: nearest zero strictly above / below this segment.
    int zp_in = SENT_LO, zp_out = SENT_LO, zn_in = SENT_HI, zn_out = SENT_HI;
    #pragma unroll
    for (int t = 0; t < NSEG; t++) {
        if (t < s) {
            zp_in  = max(zp_in,  g_lastz_in [t * NCOL + col]);
            zp_out = max(zp_out, g_lastz_out[t * NCOL + col]);
        } else if (t > s) {
            zn_in  = min(zn_in,  g_firstz_in [t * NCOL + col]);
            zn_out = min(zn_out, g_firstz_out[t * NCOL + col]);
        }
    }

    const float* m  = tgt  + b * IMG;
    const float* pr = pred + b * IMG;

    // Down pass: distance to nearest zero at-or-above.
    int lzi = zp_in, lzo = zp_out;
    #pragma unroll
    for (int r = 0; r < SEG; r++) {
        int i = base + r;
        float mv = m[i * Wn + j];
        if (mv == 0.0f) lzi = i; else lzo = i;
        s_in [r][j] = i - lzi;
        s_out[r][j] = i - lzo;
    }
    // Up pass: combine with nearest zero at-or-below, clamp to 512, square.
    // (down-distance == 0 identifies zero rows; no mask reload needed)
    int nzi = zn_in, nzo = zn_out;
    #pragma unroll
    for (int r = SEG - 1; r >= 0; r--) {
        int i = base + r;
        int di = s_in [r][j];
        int dq = s_out[r][j];
        if (di == 0) nzi = i;
        if (dq == 0) nzo = i;
        di = min(min(di, nzi - i), 512);
        dq = min(min(dq, nzo - i), 512);
        s_in [r][j] = di * di;
        s_out[r][j] = dq * dq;
    }
    __syncthreads();

    // Horizontal pass + loss terms.
    float v0 = 0.f, v1 = 0.f, v2 = 0.f, v3 = 0.f, v4 = 0.f, vmax = 0.f;
    for (int r = 0; r < SEG; r++) {
        int bi = s_in [r][j];
        int bo = s_out[r][j];
        int lim = max(bi, bo);
        for (int rad = 1; rad * rad < lim; rad++) {
            int off = rad * rad;
            int kl = j - rad;
            int kr = j + rad;
            if (kl >= 0) {
                bi = min(bi, s_in [r][kl] + off);
                bo = min(bo, s_out[r][kl] + off);
            }
            if (kr < Wn) {
                bi = min(bi, s_in [r][kr] + off);
                bo = min(bo, s_out[r][kr] + off);
            }
            lim = max(bi, bo);
        }
        float phi = sqrtf((float)bo) - sqrtf((float)bi);  // outside - inside

        int pix = (base + r) * Wn + j;
        float x  = pr[pix];
        float tv = m[pix];
        float p  = 1.0f / (1.0f + expf(-x));
        float bce = fmaxf(x, 0.0f) - x * tv + log1pf(expf(-fabsf(x)));

        v0 += p * tv;
        v1 += p;
        v2 += tv;
        v3 += bce;
        v4 += phi * p;
        vmax = fmaxf(vmax, fabsf(phi));
    }

    // Block reduction (deterministic: fixed shuffle + smem order).
    #pragma unroll
    for (int o = 16; o > 0; o >>= 1) {
        v0 += __shfl_xor_sync(0xFFFFFFFFu, v0, o);
        v1 += __shfl_xor_sync(0xFFFFFFFFu, v1, o);
        v2 += __shfl_xor_sync(0xFFFFFFFFu, v2, o);
        v3 += __shfl_xor_sync(0xFFFFFFFFu, v3, o);
        v4 += __shfl_xor_sync(0xFFFFFFFFu, v4, o);
        vmax = fmaxf(vmax, __shfl_xor_sync(0xFFFFFFFFu, vmax, o));
    }
    int w = j >> 5, l = j & 31;
    if (l == 0) {
        s_red[w][0] = v0; s_red[w][1] = v1; s_red[w][2] = v2;
        s_red[w][3] = v3; s_red[w][4] = v4; s_red[w][5] = vmax;
    }
    __syncthreads();
    if (j == 0) {
        float a0 = 0, a1 = 0, a2 = 0, a3 = 0, a4 = 0, am = 0;
        #pragma unroll
        for (int k = 0; k < 8; k++) {
            a0 += s_red[k][0]; a1 += s_red[k][1]; a2 += s_red[k][2];
            a3 += s_red[k][3]; a4 += s_red[k][4]; am = fmaxf(am, s_red[k][5]);
        }
        float* out = g_part + (b * NSEG + s) * 8;
        out[0] = a0; out[1] = a1; out[2] = a2;
        out[3] = a3; out[4] = a4; out[5] = am;
    }
}

// ---------------------------------------------------------------------------
// Final kernel: combine 128 per-block partials -> scalar loss.
// thread t = image (t/8), segment (t%8). 8-lane groups per image.
// ---------------------------------------------------------------------------
__global__ __launch_bounds__(128) void final_kernel(float* __restrict__ out) {
    __shared__ float s_img[BN];
    __shared__ float s_g[4][4];

    int t = threadIdx.x;
    const float* p = g_part + t * 8;
    float v0 = p[0], v1 = p[1], v2 = p[2], v3 = p[3], v4 = p[4], vm = p[5];

    // Per-image (8-lane segmented) reduce for boundary term.
    float st = v2, sp = v4, mx = vm;
    #pragma unroll
    for (int o = 4; o > 0; o >>= 1) {
        st += __shfl_xor_sync(0xFFFFFFFFu, st, o);
        sp += __shfl_xor_sync(0xFFFFFFFFu, sp, o);
        mx = fmaxf(mx, __shfl_xor_sync(0xFFFFFFFFu, mx, o));
    }
    if ((t & 7) == 0) {
        s_img[t >> 3] = (st > 0.0f) ? sp / (mx + 1e-8f) : 0.0f;
    }

    // Global sums v0..v3 across 128 threads.
    #pragma unroll
    for (int o = 16; o > 0; o >>= 1) {
        v0 += __shfl_xor_sync(0xFFFFFFFFu, v0, o);
        v1 += __shfl_xor_sync(0xFFFFFFFFu, v1, o);
        v2 += __shfl_xor_sync(0xFFFFFFFFu, v2, o);
        v3 += __shfl_xor_sync(0xFFFFFFFFu, v3, o);
    }
    int w = t >> 5;
    if ((t & 31) == 0) {
        s_g[w][0] = v0; s_g[w][1] = v1; s_g[w][2] = v2; s_g[w][3] = v3;
    }
    __syncthreads();

    if (t == 0) {
        float inter = 0, sum_p = 0, sum_t = 0, bces = 0;
        #pragma unroll
        for (int k = 0; k < 4; k++) {
            inter += s_g[k][0]; sum_p += s_g[k][1];
            sum_t += s_g[k][2]; bces  += s_g[k][3];
        }
        float bsum = 0;
        #pragma unroll
        for (int k = 0; k < BN; k++) bsum += s_img[k];

        float smooth   = 1e-6f;
        float dice     = 1.0f - (2.0f * inter + smooth) / (sum_p + sum_t + smooth);
        float boundary = bsum / (float)NTOT;
        float bce      = bces / (float)NTOT;
        // alpha = 0.005 -> beta = 0.595, 1-beta = 0.405
        out[0] = 0.405f * dice + 0.595f * boundary + 0.4f * bce;
    }
}

// ---------------------------------------------------------------------------
extern "C" void kernel_launch(void* const* d_in, const int* in_sizes, int n_in,
                              void* d_out, int out_size) {
    const float* pred = (const float*)d_in[0];
    const float* tgt  = (const float*)d_in[1];
    float* out = (float*)d_out;

    dim3 grid(BN, NSEG);
    carry_kernel<<<grid, 256>>>(tgt);
    fused_kernel<<<grid, 256>>>(pred, tgt);
    final_kernel<<<1, 128>>>(out);
}

// round 3
// speedup vs baseline: 4.3729x; 1.8263x over previous
#include <cuda_runtime.h>
#include <math.h>

// Problem constants
#define BN    16
#define Hn    256
#define Wn    256
#define IMG   (Hn * Wn)          // 65536
#define NTOT  (BN * IMG)         // 1048576
#define SEG   8                  // rows per fused band
#define NB    (Hn / SEG)         // 32 bands per image
#define NWORD 8                  // 256 rows / 32 bits
#define NPART (BN * NB)          // 512 partial blocks
#define SENT_LO (-1000000)
#define SENT_HI ( 1000000)

// Scratch (device globals — no allocation allowed)
// g_bits[(b*8 + w)*256 + j]: bit r set iff mask(row=w*32+r, col=j) != 0
__device__ unsigned g_bits[BN * NWORD * Wn];
__device__ float    g_part[NPART * 8];   // pt, p, t, bce, phi*p, max|phi|

// ---------------------------------------------------------------------------
// Bits kernel: build per-column occupancy bitmask. One CTA = 32 rows x 256
// cols of one image. float4 loads staged through smem, then each thread
// builds one 32-bit word for its column.
// grid: (BN, 8), block: 256
// ---------------------------------------------------------------------------
__global__ __launch_bounds__(256) void bits_kernel(const float* __restrict__ tgt) {
    __shared__ float tile[32][Wn];
    int b = blockIdx.x;
    int w = blockIdx.y;
    int tid = threadIdx.x;

    const float4* src = (const float4*)(tgt + b * IMG + w * 32 * Wn);
    #pragma unroll
    for (int k = 0; k < 8; k++) {
        int idx = tid + k * 256;            // 0..2047 float4s
        float4 v = src[idx];
        int r = idx >> 6;                   // 64 float4 per row
        int c = (idx & 63) * 4;
        tile[r][c + 0] = v.x;
        tile[r][c + 1] = v.y;
        tile[r][c + 2] = v.z;
        tile[r][c + 3] = v.w;
    }
    __syncthreads();

    unsigned wd = 0;
    #pragma unroll
    for (int r = 0; r < 32; r++) {
        wd |= (tile[r][tid] != 0.0f) ? (1u << r) : 0u;
    }
    g_bits[(b * NWORD + w) * Wn + tid] = wd;
}

// ---------------------------------------------------------------------------
// Bit-scan helpers over an 8-word (256-bit) column, absolute bit positions.
// ---------------------------------------------------------------------------
__device__ __forceinline__ int hi_below(const unsigned* Z, int base) {
    // highest set bit position < base, or SENT_LO
    int w = base >> 5;
    int off = base & 31;
    unsigned cur = off ? (Z[w] & ((1u << off) - 1u)) : 0u;
    while (true) {
        if (cur) return w * 32 + 31 - __clz(cur);
        if (--w < 0) return SENT_LO;
        cur = Z[w];
    }
}
__device__ __forceinline__ int lo_from(const unsigned* Z, int start) {
    // lowest set bit position >= start, or SENT_HI
    int w = start >> 5;
    if (w >= NWORD) return SENT_HI;
    unsigned cur = Z[w] & (0xFFFFFFFFu << (start & 31));
    while (true) {
        if (cur) return w * 32 + __ffs(cur) - 1;
        if (++w >= NWORD) return SENT_HI;
        cur = Z[w];
    }
}

// ---------------------------------------------------------------------------
// Fused kernel: one CTA = one (image, 8-row band).
//   1. vertical EDT from column bitmask (exact, int math, BIG=512 clamp)
//   2. signed combined d1^2 in smem: +d_in^2 at mask=1, -d_out^2 at mask=0
//      (complementarity: the other transform is exactly 0 at that pixel)
//   3. horizontal min_k d1sq[k]+(j-k)^2 with single-best early termination
//   4. loss terms + deterministic block reduction
// grid: (BN, 32), block: 256
// ---------------------------------------------------------------------------
__global__ __launch_bounds__(256) void fused_kernel(const float* __restrict__ pred) {
    __shared__ int   s_d[SEG][Wn];
    __shared__ float s_red[8][6];

    int b = blockIdx.x;
    int s = blockIdx.y;
    int j = threadIdx.x;
    int base = s * SEG;

    // Load this column's 256-bit occupancy mask.
    unsigned Wb[NWORD], Zin[NWORD];
    #pragma unroll
    for (int w = 0; w < NWORD; w++) {
        Wb[w]  = g_bits[(b * NWORD + w) * Wn + j];   // zeros of complement
        Zin[w] = ~Wb[w];                             // zeros of mask
    }

    // Nearest zeros strictly outside the band.
    int lzi = hi_below(Zin, base);
    int lzo = hi_below(Wb,  base);
    int nzi = lo_from(Zin, base + SEG);
    int nzo = lo_from(Wb,  base + SEG);

    // In-band bits (8 rows live inside one aligned byte of one word).
    unsigned bb = Wb[base >> 5] >> (base & 31);

    // Down pass: distance to nearest zero at-or-above.
    int ddi[SEG], ddo[SEG];
    #pragma unroll
    for (int r = 0; r < SEG; r++) {
        int i = base + r;
        if ((bb >> r) & 1) lzo = i; else lzi = i;
        ddi[r] = i - lzi;
        ddo[r] = i - lzo;
    }
    // Up pass: combine with nearest zero at-or-below, clamp 512, square, sign.
    #pragma unroll
    for (int r = SEG - 1; r >= 0; r--) {
        int i = base + r;
        int mj = (bb >> r) & 1;
        if (mj) nzo = i; else nzi = i;
        int di = min(min(ddi[r], nzi - i), 512);
        int dq = min(min(ddo[r], nzo - i), 512);
        s_d[r][j] = mj ? (di * di) : -(dq * dq);
    }
    __syncthreads();

    const float* pr = pred + b * IMG + base * Wn;

    // Horizontal pass + loss terms.
    float v0 = 0.f, v1 = 0.f, v2 = 0.f, v3 = 0.f, v4 = 0.f, vmax = 0.f;
    #pragma unroll
    for (int r = 0; r < SEG; r++) {
        int own = s_d[r][j];
        bool pos = own > 0;                  // mask bit at this pixel
        int best = pos ? own : -own;
        for (int rad = 1; rad * rad < best; rad++) {
            int off = rad * rad;
            int kl = j - rad;
            int kr = j + rad;
            if (kl >= 0) {
                int v = pos ? s_d[r][kl] : -s_d[r][kl];
                best = min(best, max(v, 0) + off);
            }
            if (kr < Wn) {
                int v = pos ? s_d[r][kr] : -s_d[r][kr];
                best = min(best, max(v, 0) + off);
            }
        }
        float dist = sqrtf((float)best);
        float phi  = pos ? -dist : dist;     // outside - inside
        float tv   = pos ? 1.0f : 0.0f;

        float x = pr[r * Wn + j];
        float p = 1.0f / (1.0f + __expf(-x));
        float bce = fmaxf(x, 0.0f) - x * tv + __logf(1.0f + __expf(-fabsf(x)));

        v0 += p * tv;
        v1 += p;
        v2 += tv;
        v3 += bce;
        v4 += phi * p;
        vmax = fmaxf(vmax, fabsf(phi));
    }

    // Deterministic block reduction.
    #pragma unroll
    for (int o = 16; o > 0; o >>= 1) {
        v0 += __shfl_xor_sync(0xFFFFFFFFu, v0, o);
        v1 += __shfl_xor_sync(0xFFFFFFFFu, v1, o);
        v2 += __shfl_xor_sync(0xFFFFFFFFu, v2, o);
        v3 += __shfl_xor_sync(0xFFFFFFFFu, v3, o);
        v4 += __shfl_xor_sync(0xFFFFFFFFu, v4, o);
        vmax = fmaxf(vmax, __shfl_xor_sync(0xFFFFFFFFu, vmax, o));
    }
    int w = j >> 5;
    if ((j & 31) == 0) {
        s_red[w][0] = v0; s_red[w][1] = v1; s_red[w][2] = v2;
        s_red[w][3] = v3; s_red[w][4] = v4; s_red[w][5] = vmax;
    }
    __syncthreads();
    if (j == 0) {
        float a0 = 0, a1 = 0, a2 = 0, a3 = 0, a4 = 0, am = 0;
        #pragma unroll
        for (int k = 0; k < 8; k++) {
            a0 += s_red[k][0]; a1 += s_red[k][1]; a2 += s_red[k][2];
            a3 += s_red[k][3]; a4 += s_red[k][4]; am = fmaxf(am, s_red[k][5]);
        }
        float* out = g_part + (b * NB + s) * 8;
        out[0] = a0; out[1] = a1; out[2] = a2;
        out[3] = a3; out[4] = a4; out[5] = am;
    }
}

// ---------------------------------------------------------------------------
// Final kernel: 512 partials -> scalar. Warp w handles image w (32 bands).
// grid: 1, block: 512
// ---------------------------------------------------------------------------
__global__ __launch_bounds__(512) void final_kernel(float* __restrict__ out) {
    __shared__ float s_img[BN];
    __shared__ float s_g[16][4];

    int t = threadIdx.x;
    const float* p = g_part + t * 8;
    float v0 = p[0], v1 = p[1], v2 = p[2], v3 = p[3], v4 = p[4], vm = p[5];

    // Per-image reduce (one warp per image) for the boundary term.
    float st = v2, sp = v4, mx = vm;
    #pragma unroll
    for (int o = 16; o > 0; o >>= 1) {
        st += __shfl_xor_sync(0xFFFFFFFFu, st, o);
        sp += __shfl_xor_sync(0xFFFFFFFFu, sp, o);
        mx = fmaxf(mx, __shfl_xor_sync(0xFFFFFFFFu, mx, o));
    }
    int w = t >> 5;
    if ((t & 31) == 0) {
        s_img[w] = (st > 0.0f) ? sp / (mx + 1e-8f) : 0.0f;
    }

    // Global sums across all 512 threads.
    #pragma unroll
    for (int o = 16; o > 0; o >>= 1) {
        v0 += __shfl_xor_sync(0xFFFFFFFFu, v0, o);
        v1 += __shfl_xor_sync(0xFFFFFFFFu, v1, o);
        v2 += __shfl_xor_sync(0xFFFFFFFFu, v2, o);
        v3 += __shfl_xor_sync(0xFFFFFFFFu, v3, o);
    }
    if ((t & 31) == 0) {
        s_g[w][0] = v0; s_g[w][1] = v1; s_g[w][2] = v2; s_g[w][3] = v3;
    }
    __syncthreads();

    if (t == 0) {
        float inter = 0, sum_p = 0, sum_t = 0, bces = 0;
        #pragma unroll
        for (int k = 0; k < 16; k++) {
            inter += s_g[k][0]; sum_p += s_g[k][1];
            sum_t += s_g[k][2]; bces  += s_g[k][3];
        }
        float bsum = 0;
        #pragma unroll
        for (int k = 0; k < BN; k++) bsum += s_img[k];

        float smooth   = 1e-6f;
        float dice     = 1.0f - (2.0f * inter + smooth) / (sum_p + sum_t + smooth);
        float boundary = bsum / (float)NTOT;
        float bce      = bces / (float)NTOT;
        // alpha = 0.005 -> beta = 0.595, 1-beta = 0.405
        out[0] = 0.405f * dice + 0.595f * boundary + 0.4f * bce;
    }
}

// ---------------------------------------------------------------------------
extern "C" void kernel_launch(void* const* d_in, const int* in_sizes, int n_in,
                              void* d_out, int out_size) {
    const float* pred = (const float*)d_in[0];
    const float* tgt  = (const float*)d_in[1];
    float* out = (float*)d_out;

    bits_kernel<<<dim3(BN, NWORD), 256>>>(tgt);
    fused_kernel<<<dim3(BN, NB), 256>>>(pred);
    final_kernel<<<1, 512>>>(out);
}